// round 14
// baseline (speedup 1.0000x reference)
#include <cuda_runtime.h>
#include <cuda_fp16.h>
#include <math.h>
#include <stdint.h>

#define KDIM   768
#define HEADS  8
#define KH     6144
#define TSEQ   1024
#define NBATCH 2
#define BT     2048
#define VOCAB  32000
#define FFD    3072

// ---------------- scratch (device globals; no runtime allocation) ----------
__device__ __half  h_xe[BT * KDIM];
__device__ __half  h_q [BT * KH];
__device__ __half  h_k [BT * KH];
__device__ __half  h_v [BT * KH];
__device__ __half  h_p [(size_t)NBATCH * HEADS * TSEQ * TSEQ];
__device__ __half  h_y [BT * KH];
__device__ float   g_t1[BT * KDIM];
__device__ __half  h_t2[BT * KDIM];
__device__ __half  h_ff[BT * FFD];
// fp16 fragment-major weights
__device__ __half hw_q [2 * KDIM * KH];
__device__ __half hw_k [2 * KDIM * KH];
__device__ __half hw_v [2 * KDIM * KH];
__device__ __half hw_u [2 * KH * KDIM];
__device__ __half hw_f1[2 * KDIM * FFD];
__device__ __half hw_f2[2 * FFD * KDIM];
__device__ __half hw_o [KDIM * VOCAB];

// ---------------- helpers ----------------------------------------------------
__device__ __forceinline__ uint32_t smem_u32(const void* p) {
    uint32_t a;
    asm("{ .reg .u64 t; cvta.to.shared.u64 t, %1; cvt.u32.u64 %0, t; }" : "=r"(a) : "l"(p));
    return a;
}
__device__ __forceinline__ void cp16(uint32_t saddr, const void* g) {
    asm volatile("cp.async.cg.shared.global [%0], [%1], 16;"
                 :: "r"(saddr), "l"(g) : "memory");
}
__device__ __forceinline__ void cp_commit() {
    asm volatile("cp.async.commit_group;" ::: "memory");
}
__device__ __forceinline__ void cp_wait2() {
    asm volatile("cp.async.wait_group 2;" ::: "memory");
}
__device__ __forceinline__ void mma16816(float c[4], uint32_t a0, uint32_t a1,
                                         uint32_t a2, uint32_t a3,
                                         uint32_t b0, uint32_t b1) {
    asm volatile(
        "mma.sync.aligned.m16n8k16.row.col.f32.f16.f16.f32 "
        "{%0,%1,%2,%3}, {%4,%5,%6,%7}, {%8,%9}, {%0,%1,%2,%3};"
        : "+f"(c[0]), "+f"(c[1]), "+f"(c[2]), "+f"(c[3])
        : "r"(a0), "r"(a1), "r"(a2), "r"(a3), "r"(b0), "r"(b1));
}
__device__ __forceinline__ uint32_t packh2(float lo, float hi) {
    __half2 h = __floats2half2_rn(lo, hi);
    return *(uint32_t*)&h;
}

// ---------------- shared epilogue ---------------------------------------------
template <int EPI, bool OUTH>
__device__ __forceinline__ void epi_store(
    float* acc, float* Cf, __half* Ch, const float* bias,
    int r0, int col, int ldc, float scale)
{
    float c0 = acc[0], c1 = acc[1], c2 = acc[2], c3 = acc[3];
    if (EPI == 1) {
        c0 *= scale; c1 *= scale; c2 *= scale; c3 *= scale;
    } else if (EPI >= 2) {
        const float b0 = bias[col], b1 = bias[col + 1];
        c0 += b0; c1 += b1; c2 += b0; c3 += b1;
        if (EPI == 3) {
            c0 = 0.5f * c0 * (1.0f + erff(c0 * 0.7071067811865476f));
            c1 = 0.5f * c1 * (1.0f + erff(c1 * 0.7071067811865476f));
            c2 = 0.5f * c2 * (1.0f + erff(c2 * 0.7071067811865476f));
            c3 = 0.5f * c3 * (1.0f + erff(c3 * 0.7071067811865476f));
        }
    }
    if (OUTH) {
        *(uint32_t*)(Ch + (size_t)r0 * ldc + col) = packh2(c0, c1);
        *(uint32_t*)(Ch + (size_t)(r0 + 8) * ldc + col) = packh2(c2, c3);
    } else {
        *(float2*)(Cf + (size_t)r0 * ldc + col) = make_float2(c0, c1);
        *(float2*)(Cf + (size_t)(r0 + 8) * ldc + col) = make_float2(c2, c3);
    }
}

// ---------------- fp16 GEMM v2: 512 thr, block 128 x BN, BK=16, 4-stage ------
// 16 warps (4M x 4N), warp tile 32 x (BN/4), 1 CTA/SM.
// Same proven k16 bank layouts as gemm_h.
template <int EPI, int BMODE, int BN, bool OUTH>
__global__ void __launch_bounds__(512) gemm_h2(
    const __half* __restrict__ A, const __half* __restrict__ B,
    void* __restrict__ Cv, const float* __restrict__ bias,
    int Kd, int lda, int ldb, int ldc,
    long long zAb, long long zAh, long long zBb, long long zBh,
    long long zCb, long long zCh, int Hn, float scale)
{
    constexpr int NT_ = BN / 32;
    constexpr int RS1 = BN * 2 + 16;
    constexpr int BSTB = (BMODE == 1) ? 16 * RS1 : BN * 32;
    constexpr int STGB = 4096 + BSTB;
    extern __shared__ char smc[];
    const uint32_t sbase = smem_u32(smc);

    const int tid = threadIdx.x;
    const int lane = tid & 31, wid = tid >> 5;
    const int g = lane >> 2, tig = lane & 3;
    const int bx = blockIdx.x, by = blockIdx.y, bz = blockIdx.z;
    float* Cf = (float*)Cv;
    __half* Ch = (__half*)Cv;
    {
        const int zb = bz / Hn, zh = bz % Hn;
        A += (size_t)zb * zAb + (size_t)zh * zAh;
        B += (size_t)zb * zBb + (size_t)zh * zBh;
        Cf += (size_t)zb * zCb + (size_t)zh * zCh;
        Ch += (size_t)zb * zCb + (size_t)zh * zCh;
    }

    // A staging: 128 rows x 2 chunks = 256 (threads 0..255)
    const int mA = (tid & 255) >> 1, cA = tid & 1;
    const __half* Ag = A + (size_t)(by * 128 + mA) * lda + cA * 8;
    const uint32_t awb = (uint32_t)(mA * 32 + ((cA * 16) ^ ((mA & 4) << 2)));

    const __half* Bg = (BMODE == 0) ? (B + (size_t)bx * BN * ldb)
                     : (BMODE == 1) ? (B + (size_t)bx * BN)
                                    : (B + (size_t)bx * BN * 16);

    float acc[2][NT_][4];
#pragma unroll
    for (int i = 0; i < 2; i++)
#pragma unroll
        for (int j = 0; j < NT_; j++)
#pragma unroll
            for (int c = 0; c < 4; c++) acc[i][j][c] = 0.f;

    const int NTILES = Kd >> 4;

    // B chunks = 2*BN (512 for BN=256, 256 for BN=128)
    auto issue = [&](int kt) {
        const uint32_t sa = sbase + (uint32_t)(kt & 3) * STGB;
        if (tid < 256) cp16(sa + awb, Ag + kt * 16);
        const uint32_t sb = sa + 4096;
        const int ch = (BN == 256) ? tid : (tid - 256);
        if (BN == 256 || tid >= 256) {
            if (BMODE == 0) {
                const int n = ch >> 1, c = ch & 1;
                cp16(sb + n * 32 + ((c * 16) ^ ((n & 4) << 2)),
                     Bg + (size_t)n * ldb + kt * 16 + c * 8);
            } else if (BMODE == 1) {
                const int k = ch / (BN / 8), c = ch % (BN / 8);
                cp16(sb + k * RS1 + c * 16,
                     Bg + (size_t)(kt * 16 + k) * ldb + c * 8);
            } else {
                cp16(sb + ch * 16, Bg + (size_t)kt * 16 * ldb + ch * 8);
            }
        }
    };

#pragma unroll
    for (int s = 0; s < 3; s++) { issue(s); cp_commit(); }

    const int wm = (wid & 3) * 32, wn = (wid >> 2) * (BN / 4);
    const int nbase = (wid >> 2) * NT_;

    for (int kt = 0; kt < NTILES; kt++) {
        cp_wait2();
        __syncthreads();

        const char* As = smc + (kt & 3) * STGB;
        const char* Bs = As + 4096;

        uint32_t af[2][4];
#pragma unroll
        for (int mt = 0; mt < 2; mt++) {
            const int m0 = wm + mt * 16 + g;
            const int sw = (m0 & 4) << 2;
            af[mt][0] = *(const uint32_t*)(As + m0 * 32 + ((tig * 4) ^ sw));
            af[mt][1] = *(const uint32_t*)(As + (m0 + 8) * 32 + ((tig * 4) ^ sw));
            af[mt][2] = *(const uint32_t*)(As + m0 * 32 + ((tig * 4 + 16) ^ sw));
            af[mt][3] = *(const uint32_t*)(As + (m0 + 8) * 32 + ((tig * 4 + 16) ^ sw));
        }

#pragma unroll
        for (int nt = 0; nt < NT_; nt++) {
            uint32_t b0, b1;
            if (BMODE == 2) {
                uint2 bv = *(const uint2*)(Bs + (nbase + nt) * 256 + lane * 8);
                b0 = bv.x; b1 = bv.y;
            } else if (BMODE == 0) {
                const int n0 = wn + nt * 8 + g;
                const int sw = (n0 & 4) << 2;
                b0 = *(const uint32_t*)(Bs + n0 * 32 + ((tig * 4) ^ sw));
                b1 = *(const uint32_t*)(Bs + n0 * 32 + ((tig * 4 + 16) ^ sw));
            } else {
                const int n0 = wn + nt * 8 + g;
                const __half* p00 = (const __half*)(Bs + (2 * tig) * RS1 + n0 * 2);
                const __half* p01 = (const __half*)(Bs + (2 * tig + 1) * RS1 + n0 * 2);
                const __half* p10 = (const __half*)(Bs + (2 * tig + 8) * RS1 + n0 * 2);
                const __half* p11 = (const __half*)(Bs + (2 * tig + 9) * RS1 + n0 * 2);
                __half2 v0 = __halves2half2(*p00, *p01);
                __half2 v1 = __halves2half2(*p10, *p11);
                b0 = *(uint32_t*)&v0; b1 = *(uint32_t*)&v1;
            }
#pragma unroll
            for (int mt = 0; mt < 2; mt++)
                mma16816(acc[mt][nt], af[mt][0], af[mt][1], af[mt][2], af[mt][3],
                         b0, b1);
        }

        if (kt + 3 < NTILES) issue(kt + 3);
        cp_commit();
    }

#pragma unroll
    for (int mt = 0; mt < 2; mt++) {
        const int r0 = by * 128 + wm + mt * 16 + g;
#pragma unroll
        for (int nt = 0; nt < NT_; nt++) {
            const int col = bx * BN + wn + nt * 8 + 2 * tig;
            epi_store<EPI, OUTH>(acc[mt][nt], Cf, Ch, bias, r0, col, ldc, scale);
        }
    }
}

// ---------------- fp16 GEMM v1: 256 thr, block 64 x BN (Wu / FFN2) ----------
template <int EPI, int BMODE, int BN, bool OUTH>
__global__ void __launch_bounds__(256, 2) gemm_h(
    const __half* __restrict__ A, const __half* __restrict__ B,
    void* __restrict__ Cv, const float* __restrict__ bias,
    int Kd, int lda, int ldb, int ldc,
    long long zAb, long long zAh, long long zBb, long long zBh,
    long long zCb, long long zCh, int Hn, float scale)
{
    constexpr int NT_ = BN / 32;
    constexpr int RS1 = BN * 2 + 16;
    constexpr int BSTB = (BMODE == 1) ? 16 * RS1 : BN * 32;
    constexpr int STGB = 2048 + BSTB;
    extern __shared__ char smc[];
    const uint32_t sbase = smem_u32(smc);

    const int tid = threadIdx.x;
    const int lane = tid & 31, wid = tid >> 5;
    const int g = lane >> 2, tig = lane & 3;
    const int bx = blockIdx.x, by = blockIdx.y, bz = blockIdx.z;
    float* Cf = (float*)Cv;
    __half* Ch = (__half*)Cv;
    {
        const int zb = bz / Hn, zh = bz % Hn;
        A += (size_t)zb * zAb + (size_t)zh * zAh;
        B += (size_t)zb * zBb + (size_t)zh * zBh;
        Cf += (size_t)zb * zCb + (size_t)zh * zCh;
        Ch += (size_t)zb * zCb + (size_t)zh * zCh;
    }

    const int mA = tid >> 1, cA = tid & 1;
    const __half* Ag = A + (size_t)(by * 64 + mA) * lda + cA * 8;
    const uint32_t awb = (uint32_t)(mA * 32 + ((cA * 16) ^ ((mA & 4) << 2)));

    const __half* Bg = (BMODE == 0) ? (B + (size_t)bx * BN * ldb)
                     : (BMODE == 1) ? (B + (size_t)bx * BN)
                                    : (B + (size_t)bx * BN * 16);

    float acc[2][NT_][4];
#pragma unroll
    for (int i = 0; i < 2; i++)
#pragma unroll
        for (int j = 0; j < NT_; j++)
#pragma unroll
            for (int c = 0; c < 4; c++) acc[i][j][c] = 0.f;

    const int NTILES = Kd >> 4;

    auto issue = [&](int kt) {
        const uint32_t sa = sbase + (uint32_t)(kt & 3) * STGB;
        if (tid < 128) cp16(sa + awb, Ag + kt * 16);
        const uint32_t sb = sa + 2048;
#pragma unroll
        for (int j = 0; j < BN / 128; j++) {
            const int ch = tid + 256 * j;
            if (BMODE == 0) {
                const int n = ch >> 1, c = ch & 1;
                cp16(sb + n * 32 + ((c * 16) ^ ((n & 4) << 2)),
                     Bg + (size_t)n * ldb + kt * 16 + c * 8);
            } else if (BMODE == 1) {
                const int k = ch / (BN / 8), c = ch % (BN / 8);
                cp16(sb + k * RS1 + c * 16,
                     Bg + (size_t)(kt * 16 + k) * ldb + c * 8);
            } else {
                cp16(sb + ch * 16, Bg + (size_t)kt * 16 * ldb + ch * 8);
            }
        }
    };

#pragma unroll
    for (int s = 0; s < 3; s++) { issue(s); cp_commit(); }

    const int wm = (wid & 1) * 32, wn = (wid >> 1) * (BN / 4);
    const int nbase = (wid >> 1) * NT_;

    for (int kt = 0; kt < NTILES; kt++) {
        cp_wait2();
        __syncthreads();

        const char* As = smc + (kt & 3) * STGB;
        const char* Bs = As + 2048;

        uint32_t af[2][4];
#pragma unroll
        for (int mt = 0; mt < 2; mt++) {
            const int m0 = wm + mt * 16 + g;
            const int sw = (m0 & 4) << 2;
            af[mt][0] = *(const uint32_t*)(As + m0 * 32 + ((tig * 4) ^ sw));
            af[mt][1] = *(const uint32_t*)(As + (m0 + 8) * 32 + ((tig * 4) ^ sw));
            af[mt][2] = *(const uint32_t*)(As + m0 * 32 + ((tig * 4 + 16) ^ sw));
            af[mt][3] = *(const uint32_t*)(As + (m0 + 8) * 32 + ((tig * 4 + 16) ^ sw));
        }

#pragma unroll
        for (int nt = 0; nt < NT_; nt++) {
            uint32_t b0, b1;
            if (BMODE == 2) {
                uint2 bv = *(const uint2*)(Bs + (nbase + nt) * 256 + lane * 8);
                b0 = bv.x; b1 = bv.y;
            } else if (BMODE == 0) {
                const int n0 = wn + nt * 8 + g;
                const int sw = (n0 & 4) << 2;
                b0 = *(const uint32_t*)(Bs + n0 * 32 + ((tig * 4) ^ sw));
                b1 = *(const uint32_t*)(Bs + n0 * 32 + ((tig * 4 + 16) ^ sw));
            } else {
                const int n0 = wn + nt * 8 + g;
                const __half* p00 = (const __half*)(Bs + (2 * tig) * RS1 + n0 * 2);
                const __half* p01 = (const __half*)(Bs + (2 * tig + 1) * RS1 + n0 * 2);
                const __half* p10 = (const __half*)(Bs + (2 * tig + 8) * RS1 + n0 * 2);
                const __half* p11 = (const __half*)(Bs + (2 * tig + 9) * RS1 + n0 * 2);
                __half2 v0 = __halves2half2(*p00, *p01);
                __half2 v1 = __halves2half2(*p10, *p11);
                b0 = *(uint32_t*)&v0; b1 = *(uint32_t*)&v1;
            }
#pragma unroll
            for (int mt = 0; mt < 2; mt++)
                mma16816(acc[mt][nt], af[mt][0], af[mt][1], af[mt][2], af[mt][3],
                         b0, b1);
        }

        if (kt + 3 < NTILES) issue(kt + 3);
        cp_commit();
    }

#pragma unroll
    for (int mt = 0; mt < 2; mt++) {
        const int r0 = by * 64 + wm + mt * 16 + g;
#pragma unroll
        for (int nt = 0; nt < NT_; nt++) {
            const int col = bx * BN + wn + nt * 8 + 2 * tig;
            epi_store<EPI, OUTH>(acc[mt][nt], Cf, Ch, bias, r0, col, ldc, scale);
        }
    }
}

// ---------------- weight -> fp16 fragment-major transform --------------------
__global__ void wcvt_h(const float* __restrict__ s, __half* __restrict__ d,
                       int N, int tot)
{
    int i = blockIdx.x * blockDim.x + threadIdx.x;
    if (i >= tot) return;
    const int lane = i & 31;
    const int rest = i >> 5;
    const int NB = N >> 3;
    const int nb = rest % NB, kb = rest / NB;
    const int gg = lane >> 2, tt = lane & 3;
    const int n = nb * 8 + gg;
    const int k0 = kb * 16 + 2 * tt;
    uint2 o;
    o.x = packh2(s[(size_t)k0 * N + n],       s[(size_t)(k0 + 1) * N + n]);
    o.y = packh2(s[(size_t)(k0 + 8) * N + n], s[(size_t)(k0 + 9) * N + n]);
    *(uint2*)&d[(size_t)kb * 16 * N + nb * 128 + lane * 4] = o;
}

// ---------------- embedding + positional encoding (fp16 out) ---------------
__global__ void embed_k(const int* __restrict__ x, const float* __restrict__ emb,
                        __half* __restrict__ xe)
{
    const int row = blockIdx.x;
    const int t = row & (TSEQ - 1);
    const int tok = x[row];
    const float* e = emb + (size_t)tok * KDIM;
    for (int c = threadIdx.x; c < KDIM; c += blockDim.x) {
        const int j = c >> 1;
        const float expo = (2.0f * (float)(2 * j)) / (float)KDIM;
        const float div = powf(10000.0f, expo);
        const float ang = (float)t / div;
        const float pe = (c & 1) ? cosf(ang) : sinf(ang);
        xe[(size_t)row * KDIM + c] = __float2half(e[c] + pe);
    }
}

// ---------------- row softmax: fp16 in-place --------------------------------
__global__ void __launch_bounds__(256) softmax_k(__half* __restrict__ s)
{
    __half* p = s + (size_t)blockIdx.x * TSEQ;
    const int tid = threadIdx.x;
    __shared__ float sh[8];

    float v[4];
    float m = -3.4e38f;
#pragma unroll
    for (int i = 0; i < 4; i++) { v[i] = __half2float(p[tid + i * 256]); m = fmaxf(m, v[i]); }
#pragma unroll
    for (int off = 16; off > 0; off >>= 1) m = fmaxf(m, __shfl_xor_sync(0xffffffffu, m, off));
    if ((tid & 31) == 0) sh[tid >> 5] = m;
    __syncthreads();
    m = fmaxf(fmaxf(fmaxf(sh[0], sh[1]), fmaxf(sh[2], sh[3])),
              fmaxf(fmaxf(sh[4], sh[5]), fmaxf(sh[6], sh[7])));
    __syncthreads();

    float sum = 0.f;
#pragma unroll
    for (int i = 0; i < 4; i++) { v[i] = expf(v[i] - m); sum += v[i]; }
#pragma unroll
    for (int off = 16; off > 0; off >>= 1) sum += __shfl_xor_sync(0xffffffffu, sum, off);
    if ((tid & 31) == 0) sh[tid >> 5] = sum;
    __syncthreads();
    sum = sh[0] + sh[1] + sh[2] + sh[3] + sh[4] + sh[5] + sh[6] + sh[7];
    const float inv = 1.0f / sum;
#pragma unroll
    for (int i = 0; i < 4; i++) p[tid + i * 256] = __float2half(v[i] * inv);
}

// ---------------- layernorm: fp32 in, fp16 out ------------------------------
__global__ void __launch_bounds__(256) ln_k(const float* __restrict__ in,
                                            __half* __restrict__ out,
                                            const float* __restrict__ gw,
                                            const float* __restrict__ bw)
{
    const float* p = in + (size_t)blockIdx.x * KDIM;
    __half* o = out + (size_t)blockIdx.x * KDIM;
    const int tid = threadIdx.x;
    __shared__ float sh[8];

    float v[3];
    float s = 0.f;
#pragma unroll
    for (int i = 0; i < 3; i++) { v[i] = p[tid + i * 256]; s += v[i]; }
#pragma unroll
    for (int off = 16; off > 0; off >>= 1) s += __shfl_xor_sync(0xffffffffu, s, off);
    if ((tid & 31) == 0) sh[tid >> 5] = s;
    __syncthreads();
    const float mu = (sh[0] + sh[1] + sh[2] + sh[3] + sh[4] + sh[5] + sh[6] + sh[7])
                     * (1.0f / (float)KDIM);
    __syncthreads();

    float vs = 0.f;
#pragma unroll
    for (int i = 0; i < 3; i++) { const float d = v[i] - mu; vs += d * d; }
#pragma unroll
    for (int off = 16; off > 0; off >>= 1) vs += __shfl_xor_sync(0xffffffffu, vs, off);
    if ((tid & 31) == 0) sh[tid >> 5] = vs;
    __syncthreads();
    const float var = (sh[0] + sh[1] + sh[2] + sh[3] + sh[4] + sh[5] + sh[6] + sh[7])
                      * (1.0f / (float)KDIM);
    const float inv = rsqrtf(var + 1e-5f);
#pragma unroll
    for (int i = 0; i < 3; i++) {
        const int c = tid + i * 256;
        o[c] = __float2half((v[i] - mu) * inv * gw[c] + bw[c]);
    }
}

// ---------------- final layernorm: fp16 in, fp16 out -------------------------
__global__ void __launch_bounds__(256) lnf_k(const __half* __restrict__ in,
                                             __half* __restrict__ out,
                                             const float* __restrict__ gw,
                                             const float* __restrict__ bw)
{
    const __half* pin = in + (size_t)blockIdx.x * KDIM;
    __half* o = out + (size_t)blockIdx.x * KDIM;
    const int tid = threadIdx.x;
    __shared__ float sh[8];

    float v[3];
    float s = 0.f;
#pragma unroll
    for (int i = 0; i < 3; i++) { v[i] = __half2float(pin[tid + i * 256]); s += v[i]; }
#pragma unroll
    for (int off = 16; off > 0; off >>= 1) s += __shfl_xor_sync(0xffffffffu, s, off);
    if ((tid & 31) == 0) sh[tid >> 5] = s;
    __syncthreads();
    const float mu = (sh[0] + sh[1] + sh[2] + sh[3] + sh[4] + sh[5] + sh[6] + sh[7])
                     * (1.0f / (float)KDIM);
    __syncthreads();

    float vs = 0.f;
#pragma unroll
    for (int i = 0; i < 3; i++) { const float d = v[i] - mu; vs += d * d; }
#pragma unroll
    for (int off = 16; off > 0; off >>= 1) vs += __shfl_xor_sync(0xffffffffu, vs, off);
    if ((tid & 31) == 0) sh[tid >> 5] = vs;
    __syncthreads();
    const float var = (sh[0] + sh[1] + sh[2] + sh[3] + sh[4] + sh[5] + sh[6] + sh[7])
                      * (1.0f / (float)KDIM);
    const float inv = rsqrtf(var + 1e-5f);
#pragma unroll
    for (int i = 0; i < 3; i++) {
        const int c = tid + i * 256;
        o[c] = __float2half((v[i] - mu) * inv * gw[c] + bw[c]);
    }
}

// ---------------- host dispatch ----------------------------------------------
template <int EPI, int BM, int BN, bool OUTH>
static inline void launch_g1(const __half* A, const __half* B, void* C,
                             const float* bias,
                             int M, int N, int Kd, int lda, int ldb, int ldc,
                             long long zAb, long long zAh, long long zBb,
                             long long zBh, long long zCb, long long zCh,
                             int Z, int Hn, float scale)
{
    constexpr int RS1 = BN * 2 + 16;
    constexpr int BSTB = (BM == 1) ? 16 * RS1 : BN * 32;
    constexpr int SMEMB = 4 * (2048 + BSTB);
    cudaFuncSetAttribute(gemm_h<EPI, BM, BN, OUTH>,
                         cudaFuncAttributeMaxDynamicSharedMemorySize, SMEMB);
    dim3 gr(N / BN, M / 64, Z);
    gemm_h<EPI, BM, BN, OUTH><<<gr, 256, SMEMB>>>(A, B, C, bias, Kd, lda, ldb, ldc,
                                                  zAb, zAh, zBb, zBh, zCb, zCh,
                                                  Hn, scale);
}

template <int EPI, int BM, int BN, bool OUTH>
static inline void launch_g2(const __half* A, const __half* B, void* C,
                             const float* bias,
                             int M, int N, int Kd, int lda, int ldb, int ldc,
                             long long zAb, long long zAh, long long zBb,
                             long long zBh, long long zCb, long long zCh,
                             int Z, int Hn, float scale)
{
    constexpr int RS1 = BN * 2 + 16;
    constexpr int BSTB = (BM == 1) ? 16 * RS1 : BN * 32;
    constexpr int SMEMB = 4 * (4096 + BSTB);
    cudaFuncSetAttribute(gemm_h2<EPI, BM, BN, OUTH>,
                         cudaFuncAttributeMaxDynamicSharedMemorySize, SMEMB);
    dim3 gr(N / BN, M / 128, Z);
    gemm_h2<EPI, BM, BN, OUTH><<<gr, 512, SMEMB>>>(A, B, C, bias, Kd, lda, ldb, ldc,
                                                   zAb, zAh, zBb, zBh, zCb, zCh,
                                                   Hn, scale);
}

static inline void wcvt(const float* s, __half* d, int K, int N)
{
    int tot = K * N / 4;
    wcvt_h<<<(tot + 255) / 256, 256>>>(s, d, N, tot);
}

extern "C" void kernel_launch(void* const* d_in, const int* in_sizes, int n_in,
                              void* d_out, int out_size)
{
    const int*   x    = (const int*)  d_in[0];
    const float* emb  = (const float*)d_in[1];
    const float* Wq   = (const float*)d_in[2];
    const float* Wk   = (const float*)d_in[3];
    const float* Wv   = (const float*)d_in[4];
    const float* Wu   = (const float*)d_in[5];
    const float* bu   = (const float*)d_in[6];
    const float* ln1g = (const float*)d_in[7];
    const float* ln1b = (const float*)d_in[8];
    const float* Wf1  = (const float*)d_in[9];
    const float* bf1  = (const float*)d_in[10];
    const float* Wf2  = (const float*)d_in[11];
    const float* bf2  = (const float*)d_in[12];
    const float* ln2g = (const float*)d_in[13];
    const float* ln2b = (const float*)d_in[14];
    const float* lnfg = (const float*)d_in[15];
    const float* lnfb = (const float*)d_in[16];
    const float* Wout = (const float*)d_in[17];
    const float* bout = (const float*)d_in[18];
    float* out = (float*)d_out;

    __half *xe, *q, *k, *v, *p, *y, *t2, *ff;
    float *t1;
    __half *wq_, *wk_, *wv_, *wu_, *wf1_, *wf2_, *wo_;
    cudaGetSymbolAddress((void**)&xe, h_xe);
    cudaGetSymbolAddress((void**)&q,  h_q);
    cudaGetSymbolAddress((void**)&k,  h_k);
    cudaGetSymbolAddress((void**)&v,  h_v);
    cudaGetSymbolAddress((void**)&p,  h_p);
    cudaGetSymbolAddress((void**)&y,  h_y);
    cudaGetSymbolAddress((void**)&t1, g_t1);
    cudaGetSymbolAddress((void**)&t2, h_t2);
    cudaGetSymbolAddress((void**)&ff, h_ff);
    cudaGetSymbolAddress((void**)&wq_,  hw_q);
    cudaGetSymbolAddress((void**)&wk_,  hw_k);
    cudaGetSymbolAddress((void**)&wv_,  hw_v);
    cudaGetSymbolAddress((void**)&wu_,  hw_u);
    cudaGetSymbolAddress((void**)&wf1_, hw_f1);
    cudaGetSymbolAddress((void**)&wf2_, hw_f2);
    cudaGetSymbolAddress((void**)&wo_,  hw_o);

    const float scale = 1.0f / sqrtf((float)KDIM);

    wcvt(Wq,   wq_,  2 * KDIM, KH);
    wcvt(Wk,   wk_,  2 * KDIM, KH);
    wcvt(Wv,   wv_,  2 * KDIM, KH);
    wcvt(Wu,   wu_,  2 * KH,   KDIM);
    wcvt(Wf1,  wf1_, 2 * KDIM, FFD);
    wcvt(Wf2,  wf2_, 2 * FFD,  KDIM);
    wcvt(Wout, wo_,  KDIM,     VOCAB);

    embed_k<<<BT, 256>>>(x, emb, xe);

    for (int l = 0; l < 2; l++) {
        const __half* lwq = wq_ + (size_t)l * KDIM * KH;
        const __half* lwk = wk_ + (size_t)l * KDIM * KH;
        const __half* lwv = wv_ + (size_t)l * KDIM * KH;
        const __half* lwu = wu_ + (size_t)l * KH * KDIM;

        // QKV: v2 kernel (128x256), FRAG weights, fp16 out
        launch_g2<0, 2, 256, true>(xe, lwq, q, nullptr, BT, KH, KDIM,
                                   KDIM, KH, KH, 0, 0, 0, 0, 0, 0, 1, 1, 0.f);
        launch_g2<0, 2, 256, true>(xe, lwk, k, nullptr, BT, KH, KDIM,
                                   KDIM, KH, KH, 0, 0, 0, 0, 0, 0, 1, 1, 0.f);
        launch_g2<0, 2, 256, true>(xe, lwv, v, nullptr, BT, KH, KDIM,
                                   KDIM, KH, KH, 0, 0, 0, 0, 0, 0, 1, 1, 0.f);

        // scores = Q K^T * scale  (v2, BMODE 0, fp16 out)
        launch_g2<1, 0, 256, true>(q, k, p, nullptr, TSEQ, TSEQ, KDIM,
                                   KH, KH, TSEQ,
                                   (long long)TSEQ * KH, KDIM,
                                   (long long)TSEQ * KH, KDIM,
                                   (long long)HEADS * TSEQ * TSEQ,
                                   (long long)TSEQ * TSEQ,
                                   NBATCH * HEADS, HEADS, scale);

        softmax_k<<<NBATCH * HEADS * TSEQ, 256>>>(p);

        // y = P @ V  (v2, BMODE 1, fp16 out)
        launch_g2<0, 1, 256, true>(p, v, y, nullptr, TSEQ, KDIM, TSEQ,
                                   TSEQ, KH, KH,
                                   (long long)HEADS * TSEQ * TSEQ,
                                   (long long)TSEQ * TSEQ,
                                   (long long)TSEQ * KH, KDIM,
                                   (long long)TSEQ * KH, KDIM,
                                   NBATCH * HEADS, HEADS, 0.f);

        // att = y @ Wu + bu (v1 kernel, FRAG, fp32 out -> LN)
        launch_g1<2, 2, 128, false>(y, lwu, t1, bu + l * KDIM, BT, KDIM, KH,
                                    KH, KDIM, KDIM, 0, 0, 0, 0, 0, 0, 1, 1, 0.f);
        ln_k<<<BT, 256>>>(t1, t2, ln1g + l * KDIM, ln1b + l * KDIM);

        // FFN1 (v2, FRAG)
        launch_g2<3, 2, 256, true>(t2, wf1_ + (size_t)l * KDIM * FFD, ff,
                                   bf1 + l * FFD, BT, FFD, KDIM,
                                   KDIM, FFD, FFD, 0, 0, 0, 0, 0, 0, 1, 1, 0.f);
        // FFN2 (v1, FRAG)
        launch_g1<2, 2, 128, false>(ff, wf2_ + (size_t)l * FFD * KDIM, t1,
                                    bf2 + l * KDIM, BT, KDIM, FFD,
                                    FFD, KDIM, KDIM, 0, 0, 0, 0, 0, 0, 1, 1, 0.f);
        ln_k<<<BT, 256>>>(t1, xe, ln2g + l * KDIM, ln2b + l * KDIM);
    }

    // final LN on fp16 xe -> fp16 t2
    lnf_k<<<BT, 256>>>(xe, t2, lnfg, lnfb);

    // logits = xf @ Wout + bout (v2, FRAG, fp32 out)
    launch_g2<2, 2, 256, false>(t2, wo_, out, bout, BT, VOCAB, KDIM,
                                KDIM, VOCAB, VOCAB, 0, 0, 0, 0, 0, 0, 1, 1, 0.f);
}

// round 15
// speedup vs baseline: 1.1566x; 1.1566x over previous
#include <cuda_runtime.h>
#include <cuda_fp16.h>
#include <math.h>
#include <stdint.h>

#define KDIM   768
#define HEADS  8
#define KH     6144
#define QKVN   18432   // 3 * KH
#define TSEQ   1024
#define NBATCH 2
#define BT     2048
#define VOCAB  32000
#define FFD    3072

// ---------------- scratch (device globals; no runtime allocation) ----------
__device__ __half  h_xe [BT * KDIM];
__device__ __half  h_qkv[(size_t)BT * QKVN];                     // q|k|v fused
__device__ __half  h_p  [(size_t)NBATCH * HEADS * TSEQ * TSEQ];  // scores/probs
__device__ __half  h_y  [BT * KH];
__device__ float   g_t1 [BT * KDIM];
__device__ __half  h_t2 [BT * KDIM];
__device__ __half  h_ff [BT * FFD];
// fp16 fragment-major weights
__device__ __half hw_qkv[(size_t)2 * KDIM * QKVN];
__device__ __half hw_u  [2 * KH * KDIM];
__device__ __half hw_f1 [2 * KDIM * FFD];
__device__ __half hw_f2 [2 * FFD * KDIM];
__device__ __half hw_o  [KDIM * VOCAB];

// ---------------- helpers ----------------------------------------------------
__device__ __forceinline__ uint32_t smem_u32(const void* p) {
    uint32_t a;
    asm("{ .reg .u64 t; cvta.to.shared.u64 t, %1; cvt.u32.u64 %0, t; }" : "=r"(a) : "l"(p));
    return a;
}
__device__ __forceinline__ void cp16(uint32_t saddr, const void* g) {
    asm volatile("cp.async.cg.shared.global [%0], [%1], 16;"
                 :: "r"(saddr), "l"(g) : "memory");
}
__device__ __forceinline__ void cp_commit() {
    asm volatile("cp.async.commit_group;" ::: "memory");
}
__device__ __forceinline__ void cp_wait2() {
    asm volatile("cp.async.wait_group 2;" ::: "memory");
}
__device__ __forceinline__ void mma16816(float c[4], uint32_t a0, uint32_t a1,
                                         uint32_t a2, uint32_t a3,
                                         uint32_t b0, uint32_t b1) {
    asm volatile(
        "mma.sync.aligned.m16n8k16.row.col.f32.f16.f16.f32 "
        "{%0,%1,%2,%3}, {%4,%5,%6,%7}, {%8,%9}, {%0,%1,%2,%3};"
        : "+f"(c[0]), "+f"(c[1]), "+f"(c[2]), "+f"(c[3])
        : "r"(a0), "r"(a1), "r"(a2), "r"(a3), "r"(b0), "r"(b1));
}
__device__ __forceinline__ uint32_t packh2(float lo, float hi) {
    __half2 h = __floats2half2_rn(lo, hi);
    return *(uint32_t*)&h;
}

// ---------------- fp16 GEMM: 256 thr, 64 x BN block, BK=16, 4-stage ---------
// 8 warps (2M x 4N), warp 32 x BN/4, 2 CTAs/SM. Proven R13 configuration.
// A smem: 64 rows x 32B, byte = m*32 + (k2B ^ ((m&4)<<2)); u32 reads.
// B smem by mode:
//  BMODE 0 (gmem [N,K] fp16): rows n x 32B, same swizzle; u32 reads
//  BMODE 1 (gmem [K,N] fp16): 16 rows x (BN*2+16)B padded; u16 reads
//  BMODE 2 (FRAG weights):    linear [nb][lane][2 u32]; one v2 read per nt
// EPI: 0 none, 1 *scale, 2 +bias, 3 +bias + exact GELU. OUTH: fp16 out.
template <int EPI, int BMODE, int BN, bool OUTH>
__global__ void __launch_bounds__(256, 2) gemm_h(
    const __half* __restrict__ A, const __half* __restrict__ B,
    void* __restrict__ Cv, const float* __restrict__ bias,
    int Kd, int lda, int ldb, int ldc,
    long long zAb, long long zAh, long long zBb, long long zBh,
    long long zCb, long long zCh, int Hn, float scale)
{
    constexpr int NT_ = BN / 32;
    constexpr int RS1 = BN * 2 + 16;
    constexpr int BSTB = (BMODE == 1) ? 16 * RS1 : BN * 32;
    constexpr int STGB = 2048 + BSTB;
    extern __shared__ char smc[];
    const uint32_t sbase = smem_u32(smc);

    const int tid = threadIdx.x;
    const int lane = tid & 31, wid = tid >> 5;
    const int g = lane >> 2, tig = lane & 3;
    const int bx = blockIdx.x, by = blockIdx.y, bz = blockIdx.z;
    float* Cf = (float*)Cv;
    __half* Ch = (__half*)Cv;
    {
        const int zb = bz / Hn, zh = bz % Hn;
        A += (size_t)zb * zAb + (size_t)zh * zAh;
        B += (size_t)zb * zBb + (size_t)zh * zBh;
        Cf += (size_t)zb * zCb + (size_t)zh * zCh;
        Ch += (size_t)zb * zCb + (size_t)zh * zCh;
    }

    const int mA = tid >> 1, cA = tid & 1;
    const __half* Ag = A + (size_t)(by * 64 + mA) * lda + cA * 8;
    const uint32_t awb = (uint32_t)(mA * 32 + ((cA * 16) ^ ((mA & 4) << 2)));

    const __half* Bg = (BMODE == 0) ? (B + (size_t)bx * BN * ldb)
                     : (BMODE == 1) ? (B + (size_t)bx * BN)
                                    : (B + (size_t)bx * BN * 16);

    float acc[2][NT_][4];
#pragma unroll
    for (int i = 0; i < 2; i++)
#pragma unroll
        for (int j = 0; j < NT_; j++)
#pragma unroll
            for (int c = 0; c < 4; c++) acc[i][j][c] = 0.f;

    const int NTILES = Kd >> 4;

    auto issue = [&](int kt) {
        const uint32_t sa = sbase + (uint32_t)(kt & 3) * STGB;
        if (tid < 128) cp16(sa + awb, Ag + kt * 16);
        const uint32_t sb = sa + 2048;
#pragma unroll
        for (int j = 0; j < BN / 128; j++) {
            const int ch = tid + 256 * j;
            if (BMODE == 0) {
                const int n = ch >> 1, c = ch & 1;
                cp16(sb + n * 32 + ((c * 16) ^ ((n & 4) << 2)),
                     Bg + (size_t)n * ldb + kt * 16 + c * 8);
            } else if (BMODE == 1) {
                const int k = ch / (BN / 8), c = ch % (BN / 8);
                cp16(sb + k * RS1 + c * 16,
                     Bg + (size_t)(kt * 16 + k) * ldb + c * 8);
            } else {
                cp16(sb + ch * 16, Bg + (size_t)kt * 16 * ldb + ch * 8);
            }
        }
    };

#pragma unroll
    for (int s = 0; s < 3; s++) { issue(s); cp_commit(); }

    const int wm = (wid & 1) * 32, wn = (wid >> 1) * (BN / 4);
    const int nbase = (wid >> 1) * NT_;

    for (int kt = 0; kt < NTILES; kt++) {
        cp_wait2();
        __syncthreads();

        const char* As = smc + (kt & 3) * STGB;
        const char* Bs = As + 2048;

        uint32_t af[2][4];
#pragma unroll
        for (int mt = 0; mt < 2; mt++) {
            const int m0 = wm + mt * 16 + g;
            const int sw = (m0 & 4) << 2;
            af[mt][0] = *(const uint32_t*)(As + m0 * 32 + ((tig * 4) ^ sw));
            af[mt][1] = *(const uint32_t*)(As + (m0 + 8) * 32 + ((tig * 4) ^ sw));
            af[mt][2] = *(const uint32_t*)(As + m0 * 32 + ((tig * 4 + 16) ^ sw));
            af[mt][3] = *(const uint32_t*)(As + (m0 + 8) * 32 + ((tig * 4 + 16) ^ sw));
        }

#pragma unroll
        for (int nt = 0; nt < NT_; nt++) {
            uint32_t b0, b1;
            if (BMODE == 2) {
                uint2 bv = *(const uint2*)(Bs + (nbase + nt) * 256 + lane * 8);
                b0 = bv.x; b1 = bv.y;
            } else if (BMODE == 0) {
                const int n0 = wn + nt * 8 + g;
                const int sw = (n0 & 4) << 2;
                b0 = *(const uint32_t*)(Bs + n0 * 32 + ((tig * 4) ^ sw));
                b1 = *(const uint32_t*)(Bs + n0 * 32 + ((tig * 4 + 16) ^ sw));
            } else {
                const int n0 = wn + nt * 8 + g;
                const __half* p00 = (const __half*)(Bs + (2 * tig) * RS1 + n0 * 2);
                const __half* p01 = (const __half*)(Bs + (2 * tig + 1) * RS1 + n0 * 2);
                const __half* p10 = (const __half*)(Bs + (2 * tig + 8) * RS1 + n0 * 2);
                const __half* p11 = (const __half*)(Bs + (2 * tig + 9) * RS1 + n0 * 2);
                __half2 v0 = __halves2half2(*p00, *p01);
                __half2 v1 = __halves2half2(*p10, *p11);
                b0 = *(uint32_t*)&v0; b1 = *(uint32_t*)&v1;
            }
#pragma unroll
            for (int mt = 0; mt < 2; mt++)
                mma16816(acc[mt][nt], af[mt][0], af[mt][1], af[mt][2], af[mt][3],
                         b0, b1);
        }

        if (kt + 3 < NTILES) issue(kt + 3);
        cp_commit();
    }

    // ---- epilogue ----
#pragma unroll
    for (int mt = 0; mt < 2; mt++) {
        const int r0 = by * 64 + wm + mt * 16 + g;
#pragma unroll
        for (int nt = 0; nt < NT_; nt++) {
            const int col = bx * BN + wn + nt * 8 + 2 * tig;
            float c0 = acc[mt][nt][0], c1 = acc[mt][nt][1];
            float c2 = acc[mt][nt][2], c3 = acc[mt][nt][3];
            if (EPI == 1) {
                c0 *= scale; c1 *= scale; c2 *= scale; c3 *= scale;
            } else if (EPI >= 2) {
                const float b0 = bias[col], b1 = bias[col + 1];
                c0 += b0; c1 += b1; c2 += b0; c3 += b1;
                if (EPI == 3) {
                    c0 = 0.5f * c0 * (1.0f + erff(c0 * 0.7071067811865476f));
                    c1 = 0.5f * c1 * (1.0f + erff(c1 * 0.7071067811865476f));
                    c2 = 0.5f * c2 * (1.0f + erff(c2 * 0.7071067811865476f));
                    c3 = 0.5f * c3 * (1.0f + erff(c3 * 0.7071067811865476f));
                }
            }
            if (OUTH) {
                *(uint32_t*)(Ch + (size_t)r0 * ldc + col) = packh2(c0, c1);
                *(uint32_t*)(Ch + (size_t)(r0 + 8) * ldc + col) = packh2(c2, c3);
            } else {
                *(float2*)(Cf + (size_t)r0 * ldc + col) = make_float2(c0, c1);
                *(float2*)(Cf + (size_t)(r0 + 8) * ldc + col) = make_float2(c2, c3);
            }
        }
    }
}

// ---------------- weight -> fp16 fragment-major transform --------------------
// src W [K, Nsrc] fp32 row-major; dst fragment-major with row width Ndst,
// column offset noff (multiple of 8).
__global__ void wcvt_h(const float* __restrict__ s, __half* __restrict__ d,
                       int Nsrc, int Ndst, int noff, int tot)
{
    int i = blockIdx.x * blockDim.x + threadIdx.x;
    if (i >= tot) return;
    const int lane = i & 31;
    const int rest = i >> 5;
    const int NB = Nsrc >> 3;
    const int nb = rest % NB, kb = rest / NB;
    const int gg = lane >> 2, tt = lane & 3;
    const int n = nb * 8 + gg;
    const int k0 = kb * 16 + 2 * tt;
    uint2 o;
    o.x = packh2(s[(size_t)k0 * Nsrc + n],       s[(size_t)(k0 + 1) * Nsrc + n]);
    o.y = packh2(s[(size_t)(k0 + 8) * Nsrc + n], s[(size_t)(k0 + 9) * Nsrc + n]);
    const int nb_d = nb + (noff >> 3);
    *(uint2*)&d[(size_t)kb * 16 * Ndst + (size_t)nb_d * 128 + lane * 4] = o;
}

// ---------------- embedding + positional encoding (fp16 out) ---------------
__global__ void embed_k(const int* __restrict__ x, const float* __restrict__ emb,
                        __half* __restrict__ xe)
{
    const int row = blockIdx.x;
    const int t = row & (TSEQ - 1);
    const int tok = x[row];
    const float* e = emb + (size_t)tok * KDIM;
    for (int c = threadIdx.x; c < KDIM; c += blockDim.x) {
        const int j = c >> 1;
        const float expo = (2.0f * (float)(2 * j)) / (float)KDIM;
        const float div = powf(10000.0f, expo);
        const float ang = (float)t / div;
        const float pe = (c & 1) ? cosf(ang) : sinf(ang);
        xe[(size_t)row * KDIM + c] = __float2half(e[c] + pe);
    }
}

// ---------------- row softmax: fp16 in-place --------------------------------
__global__ void __launch_bounds__(256) softmax_k(__half* __restrict__ s)
{
    __half* p = s + (size_t)blockIdx.x * TSEQ;
    const int tid = threadIdx.x;
    __shared__ float sh[8];

    float v[4];
    float m = -3.4e38f;
#pragma unroll
    for (int i = 0; i < 4; i++) { v[i] = __half2float(p[tid + i * 256]); m = fmaxf(m, v[i]); }
#pragma unroll
    for (int off = 16; off > 0; off >>= 1) m = fmaxf(m, __shfl_xor_sync(0xffffffffu, m, off));
    if ((tid & 31) == 0) sh[tid >> 5] = m;
    __syncthreads();
    m = fmaxf(fmaxf(fmaxf(sh[0], sh[1]), fmaxf(sh[2], sh[3])),
              fmaxf(fmaxf(sh[4], sh[5]), fmaxf(sh[6], sh[7])));
    __syncthreads();

    float sum = 0.f;
#pragma unroll
    for (int i = 0; i < 4; i++) { v[i] = expf(v[i] - m); sum += v[i]; }
#pragma unroll
    for (int off = 16; off > 0; off >>= 1) sum += __shfl_xor_sync(0xffffffffu, sum, off);
    if ((tid & 31) == 0) sh[tid >> 5] = sum;
    __syncthreads();
    sum = sh[0] + sh[1] + sh[2] + sh[3] + sh[4] + sh[5] + sh[6] + sh[7];
    const float inv = 1.0f / sum;
#pragma unroll
    for (int i = 0; i < 4; i++) p[tid + i * 256] = __float2half(v[i] * inv);
}

// ---------------- layernorm: fp32 in, fp16 out ------------------------------
__global__ void __launch_bounds__(256) ln_k(const float* __restrict__ in,
                                            __half* __restrict__ out,
                                            const float* __restrict__ gw,
                                            const float* __restrict__ bw)
{
    const float* p = in + (size_t)blockIdx.x * KDIM;
    __half* o = out + (size_t)blockIdx.x * KDIM;
    const int tid = threadIdx.x;
    __shared__ float sh[8];

    float v[3];
    float s = 0.f;
#pragma unroll
    for (int i = 0; i < 3; i++) { v[i] = p[tid + i * 256]; s += v[i]; }
#pragma unroll
    for (int off = 16; off > 0; off >>= 1) s += __shfl_xor_sync(0xffffffffu, s, off);
    if ((tid & 31) == 0) sh[tid >> 5] = s;
    __syncthreads();
    const float mu = (sh[0] + sh[1] + sh[2] + sh[3] + sh[4] + sh[5] + sh[6] + sh[7])
                     * (1.0f / (float)KDIM);
    __syncthreads();

    float vs = 0.f;
#pragma unroll
    for (int i = 0; i < 3; i++) { const float d = v[i] - mu; vs += d * d; }
#pragma unroll
    for (int off = 16; off > 0; off >>= 1) vs += __shfl_xor_sync(0xffffffffu, vs, off);
    if ((tid & 31) == 0) sh[tid >> 5] = vs;
    __syncthreads();
    const float var = (sh[0] + sh[1] + sh[2] + sh[3] + sh[4] + sh[5] + sh[6] + sh[7])
                      * (1.0f / (float)KDIM);
    const float inv = rsqrtf(var + 1e-5f);
#pragma unroll
    for (int i = 0; i < 3; i++) {
        const int c = tid + i * 256;
        o[c] = __float2half((v[i] - mu) * inv * gw[c] + bw[c]);
    }
}

// ---------------- final layernorm: fp16 in, fp16 out -------------------------
__global__ void __launch_bounds__(256) lnf_k(const __half* __restrict__ in,
                                             __half* __restrict__ out,
                                             const float* __restrict__ gw,
                                             const float* __restrict__ bw)
{
    const __half* pin = in + (size_t)blockIdx.x * KDIM;
    __half* o = out + (size_t)blockIdx.x * KDIM;
    const int tid = threadIdx.x;
    __shared__ float sh[8];

    float v[3];
    float s = 0.f;
#pragma unroll
    for (int i = 0; i < 3; i++) { v[i] = __half2float(pin[tid + i * 256]); s += v[i]; }
#pragma unroll
    for (int off = 16; off > 0; off >>= 1) s += __shfl_xor_sync(0xffffffffu, s, off);
    if ((tid & 31) == 0) sh[tid >> 5] = s;
    __syncthreads();
    const float mu = (sh[0] + sh[1] + sh[2] + sh[3] + sh[4] + sh[5] + sh[6] + sh[7])
                     * (1.0f / (float)KDIM);
    __syncthreads();

    float vs = 0.f;
#pragma unroll
    for (int i = 0; i < 3; i++) { const float d = v[i] - mu; vs += d * d; }
#pragma unroll
    for (int off = 16; off > 0; off >>= 1) vs += __shfl_xor_sync(0xffffffffu, vs, off);
    if ((tid & 31) == 0) sh[tid >> 5] = vs;
    __syncthreads();
    const float var = (sh[0] + sh[1] + sh[2] + sh[3] + sh[4] + sh[5] + sh[6] + sh[7])
                      * (1.0f / (float)KDIM);
    const float inv = rsqrtf(var + 1e-5f);
#pragma unroll
    for (int i = 0; i < 3; i++) {
        const int c = tid + i * 256;
        o[c] = __float2half((v[i] - mu) * inv * gw[c] + bw[c]);
    }
}

// ---------------- host dispatch ----------------------------------------------
template <int EPI, int BM, int BN, bool OUTH>
static inline void launch_gemm(const __half* A, const __half* B, void* C,
                               const float* bias,
                               int M, int N, int Kd, int lda, int ldb, int ldc,
                               long long zAb, long long zAh, long long zBb,
                               long long zBh, long long zCb, long long zCh,
                               int Z, int Hn, float scale)
{
    constexpr int RS1 = BN * 2 + 16;
    constexpr int BSTB = (BM == 1) ? 16 * RS1 : BN * 32;
    constexpr int SMEMB = 4 * (2048 + BSTB);
    cudaFuncSetAttribute(gemm_h<EPI, BM, BN, OUTH>,
                         cudaFuncAttributeMaxDynamicSharedMemorySize, SMEMB);
    dim3 gr(N / BN, M / 64, Z);
    gemm_h<EPI, BM, BN, OUTH><<<gr, 256, SMEMB>>>(A, B, C, bias, Kd, lda, ldb, ldc,
                                                  zAb, zAh, zBb, zBh, zCb, zCh,
                                                  Hn, scale);
}

static inline void wcvt(const float* s, __half* d, int K, int Nsrc,
                        int Ndst, int noff)
{
    int tot = K * Nsrc / 4;
    wcvt_h<<<(tot + 255) / 256, 256>>>(s, d, Nsrc, Ndst, noff, tot);
}

extern "C" void kernel_launch(void* const* d_in, const int* in_sizes, int n_in,
                              void* d_out, int out_size)
{
    const int*   x    = (const int*)  d_in[0];
    const float* emb  = (const float*)d_in[1];
    const float* Wq   = (const float*)d_in[2];
    const float* Wk   = (const float*)d_in[3];
    const float* Wv   = (const float*)d_in[4];
    const float* Wu   = (const float*)d_in[5];
    const float* bu   = (const float*)d_in[6];
    const float* ln1g = (const float*)d_in[7];
    const float* ln1b = (const float*)d_in[8];
    const float* Wf1  = (const float*)d_in[9];
    const float* bf1  = (const float*)d_in[10];
    const float* Wf2  = (const float*)d_in[11];
    const float* bf2  = (const float*)d_in[12];
    const float* ln2g = (const float*)d_in[13];
    const float* ln2b = (const float*)d_in[14];
    const float* lnfg = (const float*)d_in[15];
    const float* lnfb = (const float*)d_in[16];
    const float* Wout = (const float*)d_in[17];
    const float* bout = (const float*)d_in[18];
    float* out = (float*)d_out;

    __half *xe, *qkv, *p, *y, *t2, *ff;
    float *t1;
    __half *wqkv_, *wu_, *wf1_, *wf2_, *wo_;
    cudaGetSymbolAddress((void**)&xe,  h_xe);
    cudaGetSymbolAddress((void**)&qkv, h_qkv);
    cudaGetSymbolAddress((void**)&p,   h_p);
    cudaGetSymbolAddress((void**)&y,   h_y);
    cudaGetSymbolAddress((void**)&t1,  g_t1);
    cudaGetSymbolAddress((void**)&t2,  h_t2);
    cudaGetSymbolAddress((void**)&ff,  h_ff);
    cudaGetSymbolAddress((void**)&wqkv_, hw_qkv);
    cudaGetSymbolAddress((void**)&wu_,   hw_u);
    cudaGetSymbolAddress((void**)&wf1_,  hw_f1);
    cudaGetSymbolAddress((void**)&wf2_,  hw_f2);
    cudaGetSymbolAddress((void**)&wo_,   hw_o);

    const float scale = 1.0f / sqrtf((float)KDIM);

    // fused-layer transforms; Q/K/V interleave into combined [2K, 18432]
    wcvt(Wq,   wqkv_, 2 * KDIM, KH,   QKVN, 0);
    wcvt(Wk,   wqkv_, 2 * KDIM, KH,   QKVN, KH);
    wcvt(Wv,   wqkv_, 2 * KDIM, KH,   QKVN, 2 * KH);
    wcvt(Wu,   wu_,   2 * KH,   KDIM, KDIM, 0);
    wcvt(Wf1,  wf1_,  2 * KDIM, FFD,  FFD,  0);
    wcvt(Wf2,  wf2_,  2 * FFD,  KDIM, KDIM, 0);
    wcvt(Wout, wo_,   KDIM,     VOCAB, VOCAB, 0);

    embed_k<<<BT, 256>>>(x, emb, xe);

    for (int l = 0; l < 2; l++) {
        const __half* lwqkv = wqkv_ + (size_t)l * KDIM * QKVN;
        const __half* lwu   = wu_   + (size_t)l * KH * KDIM;
        const __half* qh = qkv;               // q columns [0, KH)
        const __half* kh = qkv + KH;          // k columns [KH, 2KH)
        const __half* vh = qkv + 2 * KH;      // v columns [2KH, 3KH)

        // fused QKV: [2048,768] x [768,18432] (FRAG), fp16 out
        launch_gemm<0, 2, 256, true>(xe, lwqkv, qkv, nullptr, BT, QKVN, KDIM,
                                     KDIM, QKVN, QKVN,
                                     0, 0, 0, 0, 0, 0, 1, 1, 0.f);

        // scores = Q K^T * scale  (BMODE 0, fp16 out)
        launch_gemm<1, 0, 256, true>(qh, kh, p, nullptr, TSEQ, TSEQ, KDIM,
                                     QKVN, QKVN, TSEQ,
                                     (long long)TSEQ * QKVN, KDIM,
                                     (long long)TSEQ * QKVN, KDIM,
                                     (long long)HEADS * TSEQ * TSEQ,
                                     (long long)TSEQ * TSEQ,
                                     NBATCH * HEADS, HEADS, scale);

        softmax_k<<<NBATCH * HEADS * TSEQ, 256>>>(p);

        // y = P @ V  (BMODE 1, BN=256, fp16 out)
        launch_gemm<0, 1, 256, true>(p, vh, y, nullptr, TSEQ, KDIM, TSEQ,
                                     TSEQ, QKVN, KH,
                                     (long long)HEADS * TSEQ * TSEQ,
                                     (long long)TSEQ * TSEQ,
                                     (long long)TSEQ * QKVN, KDIM,
                                     (long long)TSEQ * KH, KDIM,
                                     NBATCH * HEADS, HEADS, 0.f);

        // att = y @ Wu + bu (FRAG, fp32 out -> LN)
        launch_gemm<2, 2, 128, false>(y, lwu, t1, bu + l * KDIM, BT, KDIM, KH,
                                      KH, KDIM, KDIM, 0, 0, 0, 0, 0, 0, 1, 1, 0.f);
        ln_k<<<BT, 256>>>(t1, t2, ln1g + l * KDIM, ln1b + l * KDIM);

        // FFN (FRAG)
        launch_gemm<3, 2, 256, true>(t2, wf1_ + (size_t)l * KDIM * FFD, ff,
                                     bf1 + l * FFD, BT, FFD, KDIM,
                                     KDIM, FFD, FFD, 0, 0, 0, 0, 0, 0, 1, 1, 0.f);
        launch_gemm<2, 2, 128, false>(ff, wf2_ + (size_t)l * FFD * KDIM, t1,
                                      bf2 + l * KDIM, BT, KDIM, FFD,
                                      FFD, KDIM, KDIM, 0, 0, 0, 0, 0, 0, 1, 1, 0.f);
        ln_k<<<BT, 256>>>(t1, xe, ln2g + l * KDIM, ln2b + l * KDIM);
    }

    // final LN on fp16 xe -> fp16 t2
    lnf_k<<<BT, 256>>>(xe, t2, lnfg, lnfb);

    // logits = xf @ Wout + bout (FRAG, fp32 out)
    launch_gemm<2, 2, 256, false>(t2, wo_, out, bout, BT, VOCAB, KDIM,
                                  KDIM, VOCAB, VOCAB, 0, 0, 0, 0, 0, 0, 1, 1, 0.f);
}

// round 16
// speedup vs baseline: 1.1774x; 1.0179x over previous
#include <cuda_runtime.h>
#include <cuda_fp16.h>
#include <math.h>
#include <stdint.h>

#define KDIM   768
#define HEADS  8
#define KH     6144
#define QKVN   18432   // 3 * KH
#define TSEQ   1024
#define NBATCH 2
#define BT     2048
#define VOCAB  32000
#define FFD    3072

// ---------------- scratch (device globals; no runtime allocation) ----------
__device__ __half  h_xe [BT * KDIM];
__device__ __half  h_qkv[(size_t)BT * QKVN];                     // q|k|v fused
__device__ __half  h_p  [(size_t)NBATCH * HEADS * TSEQ * TSEQ];  // scores/probs
__device__ __half  h_y  [BT * KH];
__device__ float   g_t1 [2 * BT * KDIM];                         // split-K partials
__device__ __half  h_t2 [BT * KDIM];
__device__ __half  h_ff [BT * FFD];
// fp16 fragment-major weights
__device__ __half hw_qkv[(size_t)2 * KDIM * QKVN];
__device__ __half hw_u  [2 * KH * KDIM];
__device__ __half hw_f1 [2 * KDIM * FFD];
__device__ __half hw_f2 [2 * FFD * KDIM];
__device__ __half hw_o  [KDIM * VOCAB];

// ---------------- helpers ----------------------------------------------------
__device__ __forceinline__ uint32_t smem_u32(const void* p) {
    uint32_t a;
    asm("{ .reg .u64 t; cvta.to.shared.u64 t, %1; cvt.u32.u64 %0, t; }" : "=r"(a) : "l"(p));
    return a;
}
__device__ __forceinline__ void cp16(uint32_t saddr, const void* g) {
    asm volatile("cp.async.cg.shared.global [%0], [%1], 16;"
                 :: "r"(saddr), "l"(g) : "memory");
}
__device__ __forceinline__ void cp_commit() {
    asm volatile("cp.async.commit_group;" ::: "memory");
}
__device__ __forceinline__ void cp_wait2() {
    asm volatile("cp.async.wait_group 2;" ::: "memory");
}
__device__ __forceinline__ void mma16816(float c[4], uint32_t a0, uint32_t a1,
                                         uint32_t a2, uint32_t a3,
                                         uint32_t b0, uint32_t b1) {
    asm volatile(
        "mma.sync.aligned.m16n8k16.row.col.f32.f16.f16.f32 "
        "{%0,%1,%2,%3}, {%4,%5,%6,%7}, {%8,%9}, {%0,%1,%2,%3};"
        : "+f"(c[0]), "+f"(c[1]), "+f"(c[2]), "+f"(c[3])
        : "r"(a0), "r"(a1), "r"(a2), "r"(a3), "r"(b0), "r"(b1));
}
__device__ __forceinline__ uint32_t packh2(float lo, float hi) {
    __half2 h = __floats2half2_rn(lo, hi);
    return *(uint32_t*)&h;
}

// ---------------- fp16 GEMM: 256 thr, 64 x BN block, BK=16, 4-stage ---------
// 8 warps (2M x 4N), warp 32 x BN/4, 2 CTAs/SM. Proven R13/R15 configuration.
// BMODE 0: gmem [N,K]; BMODE 1: gmem [K,N] padded; BMODE 2: FRAG weights.
// EPI: 0 none, 1 *scale, 2 +bias, 3 +bias + exact GELU. OUTH: fp16 out.
template <int EPI, int BMODE, int BN, bool OUTH>
__global__ void __launch_bounds__(256, 2) gemm_h(
    const __half* __restrict__ A, const __half* __restrict__ B,
    void* __restrict__ Cv, const float* __restrict__ bias,
    int Kd, int lda, int ldb, int ldc,
    long long zAb, long long zAh, long long zBb, long long zBh,
    long long zCb, long long zCh, int Hn, float scale)
{
    constexpr int NT_ = BN / 32;
    constexpr int RS1 = BN * 2 + 16;
    constexpr int BSTB = (BMODE == 1) ? 16 * RS1 : BN * 32;
    constexpr int STGB = 2048 + BSTB;
    extern __shared__ char smc[];
    const uint32_t sbase = smem_u32(smc);

    const int tid = threadIdx.x;
    const int lane = tid & 31, wid = tid >> 5;
    const int g = lane >> 2, tig = lane & 3;
    const int bx = blockIdx.x, by = blockIdx.y, bz = blockIdx.z;
    float* Cf = (float*)Cv;
    __half* Ch = (__half*)Cv;
    {
        const int zb = bz / Hn, zh = bz % Hn;
        A += (size_t)zb * zAb + (size_t)zh * zAh;
        B += (size_t)zb * zBb + (size_t)zh * zBh;
        Cf += (size_t)zb * zCb + (size_t)zh * zCh;
        Ch += (size_t)zb * zCb + (size_t)zh * zCh;
    }

    const int mA = tid >> 1, cA = tid & 1;
    const __half* Ag = A + (size_t)(by * 64 + mA) * lda + cA * 8;
    const uint32_t awb = (uint32_t)(mA * 32 + ((cA * 16) ^ ((mA & 4) << 2)));

    const __half* Bg = (BMODE == 0) ? (B + (size_t)bx * BN * ldb)
                     : (BMODE == 1) ? (B + (size_t)bx * BN)
                                    : (B + (size_t)bx * BN * 16);

    float acc[2][NT_][4];
#pragma unroll
    for (int i = 0; i < 2; i++)
#pragma unroll
        for (int j = 0; j < NT_; j++)
#pragma unroll
            for (int c = 0; c < 4; c++) acc[i][j][c] = 0.f;

    const int NTILES = Kd >> 4;

    auto issue = [&](int kt) {
        const uint32_t sa = sbase + (uint32_t)(kt & 3) * STGB;
        if (tid < 128) cp16(sa + awb, Ag + kt * 16);
        const uint32_t sb = sa + 2048;
#pragma unroll
        for (int j = 0; j < BN / 128; j++) {
            const int ch = tid + 256 * j;
            if (BMODE == 0) {
                const int n = ch >> 1, c = ch & 1;
                cp16(sb + n * 32 + ((c * 16) ^ ((n & 4) << 2)),
                     Bg + (size_t)n * ldb + kt * 16 + c * 8);
            } else if (BMODE == 1) {
                const int k = ch / (BN / 8), c = ch % (BN / 8);
                cp16(sb + k * RS1 + c * 16,
                     Bg + (size_t)(kt * 16 + k) * ldb + c * 8);
            } else {
                cp16(sb + ch * 16, Bg + (size_t)kt * 16 * ldb + ch * 8);
            }
        }
    };

#pragma unroll
    for (int s = 0; s < 3; s++) { issue(s); cp_commit(); }

    const int wm = (wid & 1) * 32, wn = (wid >> 1) * (BN / 4);
    const int nbase = (wid >> 1) * NT_;

    for (int kt = 0; kt < NTILES; kt++) {
        cp_wait2();
        __syncthreads();

        const char* As = smc + (kt & 3) * STGB;
        const char* Bs = As + 2048;

        uint32_t af[2][4];
#pragma unroll
        for (int mt = 0; mt < 2; mt++) {
            const int m0 = wm + mt * 16 + g;
            const int sw = (m0 & 4) << 2;
            af[mt][0] = *(const uint32_t*)(As + m0 * 32 + ((tig * 4) ^ sw));
            af[mt][1] = *(const uint32_t*)(As + (m0 + 8) * 32 + ((tig * 4) ^ sw));
            af[mt][2] = *(const uint32_t*)(As + m0 * 32 + ((tig * 4 + 16) ^ sw));
            af[mt][3] = *(const uint32_t*)(As + (m0 + 8) * 32 + ((tig * 4 + 16) ^ sw));
        }

#pragma unroll
        for (int nt = 0; nt < NT_; nt++) {
            uint32_t b0, b1;
            if (BMODE == 2) {
                uint2 bv = *(const uint2*)(Bs + (nbase + nt) * 256 + lane * 8);
                b0 = bv.x; b1 = bv.y;
            } else if (BMODE == 0) {
                const int n0 = wn + nt * 8 + g;
                const int sw = (n0 & 4) << 2;
                b0 = *(const uint32_t*)(Bs + n0 * 32 + ((tig * 4) ^ sw));
                b1 = *(const uint32_t*)(Bs + n0 * 32 + ((tig * 4 + 16) ^ sw));
            } else {
                const int n0 = wn + nt * 8 + g;
                const __half* p00 = (const __half*)(Bs + (2 * tig) * RS1 + n0 * 2);
                const __half* p01 = (const __half*)(Bs + (2 * tig + 1) * RS1 + n0 * 2);
                const __half* p10 = (const __half*)(Bs + (2 * tig + 8) * RS1 + n0 * 2);
                const __half* p11 = (const __half*)(Bs + (2 * tig + 9) * RS1 + n0 * 2);
                __half2 v0 = __halves2half2(*p00, *p01);
                __half2 v1 = __halves2half2(*p10, *p11);
                b0 = *(uint32_t*)&v0; b1 = *(uint32_t*)&v1;
            }
#pragma unroll
            for (int mt = 0; mt < 2; mt++)
                mma16816(acc[mt][nt], af[mt][0], af[mt][1], af[mt][2], af[mt][3],
                         b0, b1);
        }

        if (kt + 3 < NTILES) issue(kt + 3);
        cp_commit();
    }

    // ---- epilogue ----
#pragma unroll
    for (int mt = 0; mt < 2; mt++) {
        const int r0 = by * 64 + wm + mt * 16 + g;
#pragma unroll
        for (int nt = 0; nt < NT_; nt++) {
            const int col = bx * BN + wn + nt * 8 + 2 * tig;
            float c0 = acc[mt][nt][0], c1 = acc[mt][nt][1];
            float c2 = acc[mt][nt][2], c3 = acc[mt][nt][3];
            if (EPI == 1) {
                c0 *= scale; c1 *= scale; c2 *= scale; c3 *= scale;
            } else if (EPI >= 2) {
                const float b0 = bias[col], b1 = bias[col + 1];
                c0 += b0; c1 += b1; c2 += b0; c3 += b1;
                if (EPI == 3) {
                    c0 = 0.5f * c0 * (1.0f + erff(c0 * 0.7071067811865476f));
                    c1 = 0.5f * c1 * (1.0f + erff(c1 * 0.7071067811865476f));
                    c2 = 0.5f * c2 * (1.0f + erff(c2 * 0.7071067811865476f));
                    c3 = 0.5f * c3 * (1.0f + erff(c3 * 0.7071067811865476f));
                }
            }
            if (OUTH) {
                *(uint32_t*)(Ch + (size_t)r0 * ldc + col) = packh2(c0, c1);
                *(uint32_t*)(Ch + (size_t)(r0 + 8) * ldc + col) = packh2(c2, c3);
            } else {
                *(float2*)(Cf + (size_t)r0 * ldc + col) = make_float2(c0, c1);
                *(float2*)(Cf + (size_t)(r0 + 8) * ldc + col) = make_float2(c2, c3);
            }
        }
    }
}

// ---------------- weight -> fp16 fragment-major transform --------------------
__global__ void wcvt_h(const float* __restrict__ s, __half* __restrict__ d,
                       int Nsrc, int Ndst, int noff, int tot)
{
    int i = blockIdx.x * blockDim.x + threadIdx.x;
    if (i >= tot) return;
    const int lane = i & 31;
    const int rest = i >> 5;
    const int NB = Nsrc >> 3;
    const int nb = rest % NB, kb = rest / NB;
    const int gg = lane >> 2, tt = lane & 3;
    const int n = nb * 8 + gg;
    const int k0 = kb * 16 + 2 * tt;
    uint2 o;
    o.x = packh2(s[(size_t)k0 * Nsrc + n],       s[(size_t)(k0 + 1) * Nsrc + n]);
    o.y = packh2(s[(size_t)(k0 + 8) * Nsrc + n], s[(size_t)(k0 + 9) * Nsrc + n]);
    const int nb_d = nb + (noff >> 3);
    *(uint2*)&d[(size_t)kb * 16 * Ndst + (size_t)nb_d * 128 + lane * 4] = o;
}

// ---------------- embedding + positional encoding (fp16 out) ---------------
__global__ void embed_k(const int* __restrict__ x, const float* __restrict__ emb,
                        __half* __restrict__ xe)
{
    const int row = blockIdx.x;
    const int t = row & (TSEQ - 1);
    const int tok = x[row];
    const float* e = emb + (size_t)tok * KDIM;
    for (int c = threadIdx.x; c < KDIM; c += blockDim.x) {
        const int j = c >> 1;
        const float expo = (2.0f * (float)(2 * j)) / (float)KDIM;
        const float div = powf(10000.0f, expo);
        const float ang = (float)t / div;
        const float pe = (c & 1) ? cosf(ang) : sinf(ang);
        xe[(size_t)row * KDIM + c] = __float2half(e[c] + pe);
    }
}

// ---------------- row softmax: fp16 in-place --------------------------------
__global__ void __launch_bounds__(256) softmax_k(__half* __restrict__ s)
{
    __half* p = s + (size_t)blockIdx.x * TSEQ;
    const int tid = threadIdx.x;
    __shared__ float sh[8];

    float v[4];
    float m = -3.4e38f;
#pragma unroll
    for (int i = 0; i < 4; i++) { v[i] = __half2float(p[tid + i * 256]); m = fmaxf(m, v[i]); }
#pragma unroll
    for (int off = 16; off > 0; off >>= 1) m = fmaxf(m, __shfl_xor_sync(0xffffffffu, m, off));
    if ((tid & 31) == 0) sh[tid >> 5] = m;
    __syncthreads();
    m = fmaxf(fmaxf(fmaxf(sh[0], sh[1]), fmaxf(sh[2], sh[3])),
              fmaxf(fmaxf(sh[4], sh[5]), fmaxf(sh[6], sh[7])));
    __syncthreads();

    float sum = 0.f;
#pragma unroll
    for (int i = 0; i < 4; i++) { v[i] = expf(v[i] - m); sum += v[i]; }
#pragma unroll
    for (int off = 16; off > 0; off >>= 1) sum += __shfl_xor_sync(0xffffffffu, sum, off);
    if ((tid & 31) == 0) sh[tid >> 5] = sum;
    __syncthreads();
    sum = sh[0] + sh[1] + sh[2] + sh[3] + sh[4] + sh[5] + sh[6] + sh[7];
    const float inv = 1.0f / sum;
#pragma unroll
    for (int i = 0; i < 4; i++) p[tid + i * 256] = __float2half(v[i] * inv);
}

// ---------------- layernorm over (a + b + bias): fp32x2 in, fp16 out --------
__global__ void __launch_bounds__(256) lnsum_k(const float* __restrict__ ina,
                                               const float* __restrict__ inb,
                                               const float* __restrict__ bias,
                                               __half* __restrict__ out,
                                               const float* __restrict__ gw,
                                               const float* __restrict__ bw)
{
    const float* pa = ina + (size_t)blockIdx.x * KDIM;
    const float* pb = inb + (size_t)blockIdx.x * KDIM;
    __half* o = out + (size_t)blockIdx.x * KDIM;
    const int tid = threadIdx.x;
    __shared__ float sh[8];

    float v[3];
    float s = 0.f;
#pragma unroll
    for (int i = 0; i < 3; i++) {
        const int c = tid + i * 256;
        v[i] = pa[c] + pb[c] + bias[c];
        s += v[i];
    }
#pragma unroll
    for (int off = 16; off > 0; off >>= 1) s += __shfl_xor_sync(0xffffffffu, s, off);
    if ((tid & 31) == 0) sh[tid >> 5] = s;
    __syncthreads();
    const float mu = (sh[0] + sh[1] + sh[2] + sh[3] + sh[4] + sh[5] + sh[6] + sh[7])
                     * (1.0f / (float)KDIM);
    __syncthreads();

    float vs = 0.f;
#pragma unroll
    for (int i = 0; i < 3; i++) { const float d = v[i] - mu; vs += d * d; }
#pragma unroll
    for (int off = 16; off > 0; off >>= 1) vs += __shfl_xor_sync(0xffffffffu, vs, off);
    if ((tid & 31) == 0) sh[tid >> 5] = vs;
    __syncthreads();
    const float var = (sh[0] + sh[1] + sh[2] + sh[3] + sh[4] + sh[5] + sh[6] + sh[7])
                      * (1.0f / (float)KDIM);
    const float inv = rsqrtf(var + 1e-5f);
#pragma unroll
    for (int i = 0; i < 3; i++) {
        const int c = tid + i * 256;
        o[c] = __float2half((v[i] - mu) * inv * gw[c] + bw[c]);
    }
}

// ---------------- final layernorm: fp16 in, fp16 out -------------------------
__global__ void __launch_bounds__(256) lnf_k(const __half* __restrict__ in,
                                             __half* __restrict__ out,
                                             const float* __restrict__ gw,
                                             const float* __restrict__ bw)
{
    const __half* pin = in + (size_t)blockIdx.x * KDIM;
    __half* o = out + (size_t)blockIdx.x * KDIM;
    const int tid = threadIdx.x;
    __shared__ float sh[8];

    float v[3];
    float s = 0.f;
#pragma unroll
    for (int i = 0; i < 3; i++) { v[i] = __half2float(pin[tid + i * 256]); s += v[i]; }
#pragma unroll
    for (int off = 16; off > 0; off >>= 1) s += __shfl_xor_sync(0xffffffffu, s, off);
    if ((tid & 31) == 0) sh[tid >> 5] = s;
    __syncthreads();
    const float mu = (sh[0] + sh[1] + sh[2] + sh[3] + sh[4] + sh[5] + sh[6] + sh[7])
                     * (1.0f / (float)KDIM);
    __syncthreads();

    float vs = 0.f;
#pragma unroll
    for (int i = 0; i < 3; i++) { const float d = v[i] - mu; vs += d * d; }
#pragma unroll
    for (int off = 16; off > 0; off >>= 1) vs += __shfl_xor_sync(0xffffffffu, vs, off);
    if ((tid & 31) == 0) sh[tid >> 5] = vs;
    __syncthreads();
    const float var = (sh[0] + sh[1] + sh[2] + sh[3] + sh[4] + sh[5] + sh[6] + sh[7])
                      * (1.0f / (float)KDIM);
    const float inv = rsqrtf(var + 1e-5f);
#pragma unroll
    for (int i = 0; i < 3; i++) {
        const int c = tid + i * 256;
        o[c] = __float2half((v[i] - mu) * inv * gw[c] + bw[c]);
    }
}

// ---------------- host dispatch ----------------------------------------------
template <int EPI, int BM, int BN, bool OUTH>
static inline void launch_gemm(const __half* A, const __half* B, void* C,
                               const float* bias,
                               int M, int N, int Kd, int lda, int ldb, int ldc,
                               long long zAb, long long zAh, long long zBb,
                               long long zBh, long long zCb, long long zCh,
                               int Z, int Hn, float scale)
{
    constexpr int RS1 = BN * 2 + 16;
    constexpr int BSTB = (BM == 1) ? 16 * RS1 : BN * 32;
    constexpr int SMEMB = 4 * (2048 + BSTB);
    cudaFuncSetAttribute(gemm_h<EPI, BM, BN, OUTH>,
                         cudaFuncAttributeMaxDynamicSharedMemorySize, SMEMB);
    dim3 gr(N / BN, M / 64, Z);
    gemm_h<EPI, BM, BN, OUTH><<<gr, 256, SMEMB>>>(A, B, C, bias, Kd, lda, ldb, ldc,
                                                  zAb, zAh, zBb, zBh, zCb, zCh,
                                                  Hn, scale);
}

static inline void wcvt(const float* s, __half* d, int K, int Nsrc,
                        int Ndst, int noff)
{
    int tot = K * Nsrc / 4;
    wcvt_h<<<(tot + 255) / 256, 256>>>(s, d, Nsrc, Ndst, noff, tot);
}

extern "C" void kernel_launch(void* const* d_in, const int* in_sizes, int n_in,
                              void* d_out, int out_size)
{
    const int*   x    = (const int*)  d_in[0];
    const float* emb  = (const float*)d_in[1];
    const float* Wq   = (const float*)d_in[2];
    const float* Wk   = (const float*)d_in[3];
    const float* Wv   = (const float*)d_in[4];
    const float* Wu   = (const float*)d_in[5];
    const float* bu   = (const float*)d_in[6];
    const float* ln1g = (const float*)d_in[7];
    const float* ln1b = (const float*)d_in[8];
    const float* Wf1  = (const float*)d_in[9];
    const float* bf1  = (const float*)d_in[10];
    const float* Wf2  = (const float*)d_in[11];
    const float* bf2  = (const float*)d_in[12];
    const float* ln2g = (const float*)d_in[13];
    const float* ln2b = (const float*)d_in[14];
    const float* lnfg = (const float*)d_in[15];
    const float* lnfb = (const float*)d_in[16];
    const float* Wout = (const float*)d_in[17];
    const float* bout = (const float*)d_in[18];
    float* out = (float*)d_out;

    __half *xe, *qkv, *p, *y, *t2, *ff;
    float *t1;
    __half *wqkv_, *wu_, *wf1_, *wf2_, *wo_;
    cudaGetSymbolAddress((void**)&xe,  h_xe);
    cudaGetSymbolAddress((void**)&qkv, h_qkv);
    cudaGetSymbolAddress((void**)&p,   h_p);
    cudaGetSymbolAddress((void**)&y,   h_y);
    cudaGetSymbolAddress((void**)&t1,  g_t1);
    cudaGetSymbolAddress((void**)&t2,  h_t2);
    cudaGetSymbolAddress((void**)&ff,  h_ff);
    cudaGetSymbolAddress((void**)&wqkv_, hw_qkv);
    cudaGetSymbolAddress((void**)&wu_,   hw_u);
    cudaGetSymbolAddress((void**)&wf1_,  hw_f1);
    cudaGetSymbolAddress((void**)&wf2_,  hw_f2);
    cudaGetSymbolAddress((void**)&wo_,   hw_o);

    const float scale = 1.0f / sqrtf((float)KDIM);
    float* t1b = t1 + (size_t)BT * KDIM;

    wcvt(Wq,   wqkv_, 2 * KDIM, KH,   QKVN, 0);
    wcvt(Wk,   wqkv_, 2 * KDIM, KH,   QKVN, KH);
    wcvt(Wv,   wqkv_, 2 * KDIM, KH,   QKVN, 2 * KH);
    wcvt(Wu,   wu_,   2 * KH,   KDIM, KDIM, 0);
    wcvt(Wf1,  wf1_,  2 * KDIM, FFD,  FFD,  0);
    wcvt(Wf2,  wf2_,  2 * FFD,  KDIM, KDIM, 0);
    wcvt(Wout, wo_,   KDIM,     VOCAB, VOCAB, 0);

    embed_k<<<BT, 256>>>(x, emb, xe);

    for (int l = 0; l < 2; l++) {
        const __half* lwqkv = wqkv_ + (size_t)l * KDIM * QKVN;
        const __half* lwu   = wu_   + (size_t)l * KH * KDIM;
        const __half* qh = qkv;
        const __half* kh = qkv + KH;
        const __half* vh = qkv + 2 * KH;

        // fused QKV: [2048,768] x [768,18432] (FRAG), fp16 out
        launch_gemm<0, 2, 256, true>(xe, lwqkv, qkv, nullptr, BT, QKVN, KDIM,
                                     KDIM, QKVN, QKVN,
                                     0, 0, 0, 0, 0, 0, 1, 1, 0.f);

        // scores = Q K^T * scale  (BMODE 0, fp16 out)
        launch_gemm<1, 0, 256, true>(qh, kh, p, nullptr, TSEQ, TSEQ, KDIM,
                                     QKVN, QKVN, TSEQ,
                                     (long long)TSEQ * QKVN, KDIM,
                                     (long long)TSEQ * QKVN, KDIM,
                                     (long long)HEADS * TSEQ * TSEQ,
                                     (long long)TSEQ * TSEQ,
                                     NBATCH * HEADS, HEADS, scale);

        softmax_k<<<NBATCH * HEADS * TSEQ, 256>>>(p);

        // y = P @ V  (BMODE 1, BN=256, fp16 out)
        launch_gemm<0, 1, 256, true>(p, vh, y, nullptr, TSEQ, KDIM, TSEQ,
                                     TSEQ, QKVN, KH,
                                     (long long)HEADS * TSEQ * TSEQ,
                                     (long long)TSEQ * TSEQ,
                                     (long long)TSEQ * QKVN, KDIM,
                                     (long long)TSEQ * KH, KDIM,
                                     NBATCH * HEADS, HEADS, 0.f);

        // att partials: split-K=2 over KH (FRAG); bias folded into lnsum
        launch_gemm<0, 2, 128, false>(y, lwu, t1, nullptr, BT, KDIM, KH / 2,
                                      KH, KDIM, KDIM,
                                      0, KH / 2,
                                      0, (long long)(KH / 2) * KDIM,
                                      0, (long long)BT * KDIM,
                                      2, 2, 0.f);
        lnsum_k<<<BT, 256>>>(t1, t1b, bu + l * KDIM, t2,
                             ln1g + l * KDIM, ln1b + l * KDIM);

        // FFN1 (FRAG, GELU, fp16 out)
        launch_gemm<3, 2, 256, true>(t2, wf1_ + (size_t)l * KDIM * FFD, ff,
                                     bf1 + l * FFD, BT, FFD, KDIM,
                                     KDIM, FFD, FFD, 0, 0, 0, 0, 0, 0, 1, 1, 0.f);
        // FFN2 partials: split-K=2 over FFD (FRAG)
        launch_gemm<0, 2, 128, false>(ff, wf2_ + (size_t)l * FFD * KDIM, t1,
                                      nullptr, BT, KDIM, FFD / 2,
                                      FFD, KDIM, KDIM,
                                      0, FFD / 2,
                                      0, (long long)(FFD / 2) * KDIM,
                                      0, (long long)BT * KDIM,
                                      2, 2, 0.f);
        lnsum_k<<<BT, 256>>>(t1, t1b, bf2 + l * KDIM, xe,
                             ln2g + l * KDIM, ln2b + l * KDIM);
    }

    // final LN on fp16 xe -> fp16 t2
    lnf_k<<<BT, 256>>>(xe, t2, lnfg, lnfb);

    // logits = xf @ Wout + bout (FRAG, fp32 out)
    launch_gemm<2, 2, 256, false>(t2, wo_, out, bout, BT, VOCAB, KDIM,
                                  KDIM, VOCAB, VOCAB, 0, 0, 0, 0, 0, 0, 1, 1, 0.f);
}